// round 16
// baseline (speedup 1.0000x reference)
#include <cuda_runtime.h>
#include <cuda_bf16.h>
#include <stdint.h>
#include <math.h>

#define BB 128
#define TT 12
#define NA 207
#define FF 14
#define HID 128
#define G3 384
#define TOPKN 10
#define HZN 12
#define BN (BB*NA)
#define BTN (BB*TT*NA)
#define ZP 96
#define KC 208
#define LROWS 256

__device__ float    g_emb[BN*16];
__device__ float    g_L[(size_t)BB*NA*NA];
__device__ uint32_t g_Lp[(size_t)BB*LROWS*KC];
__device__ float    g_R0[(size_t)BN*G3];
__device__ float    g_R1[(size_t)BN*G3];
__device__ float    g_R2[(size_t)BN*G3];
__device__ uint32_t g_R2t[(size_t)BB*G3*KC];
__device__ uint32_t g_Vt[(size_t)BB*G3*KC];
__device__ float    g_S[(size_t)BN*G3];
__device__ float    g_cemb[(size_t)BTN*32];
__device__ uint32_t g_z[(size_t)BTN*ZP];    // natural (b,t,n) row order
__device__ float    g_gx[(size_t)BTN*G3];   // [t][gate*128+j][q]
__device__ float    g_scal[2];
__device__ uint32_t g_wihp[G3*ZP];
__device__ uint32_t g_ewhhp[G3*HID];
__device__ uint32_t g_dwhhp[G3*HID];
__device__ uint32_t g_dwihp[G3*32];
__device__ float    g_bC[G3];
__device__ float    g_dbC[G3];

__device__ __forceinline__ float sigm(float x){ return 1.f/(1.f+expf(-x)); }
__device__ __forceinline__ uint32_t pack_split(float x){
    __nv_bfloat16 h = __float2bfloat16(x);
    float hr = __bfloat162float(h);
    __nv_bfloat16 l = __float2bfloat16(x - hr);
    return (uint32_t)__bfloat16_as_ushort(h) | ((uint32_t)__bfloat16_as_ushort(l) << 16);
}
__device__ __forceinline__ float unpk(uint32_t p){
    return __bfloat162float(__ushort_as_bfloat16((unsigned short)(p & 0xffffu)))
         + __bfloat162float(__ushort_as_bfloat16((unsigned short)(p >> 16)));
}
__device__ __forceinline__ void cpa(uint32_t dst, const void* src){
    asm volatile("cp.async.cg.shared.global [%0], [%1], 16;" :: "r"(dst), "l"(src));
}
__device__ __forceinline__ void mma_bf16(float* c, const uint32_t* a, uint32_t b0, uint32_t b1){
    asm volatile("mma.sync.aligned.m16n8k16.row.col.f32.bf16.bf16.f32 "
        "{%0,%1,%2,%3}, {%4,%5,%6,%7}, {%8,%9}, {%0,%1,%2,%3};"
        : "+f"(c[0]),"+f"(c[1]),"+f"(c[2]),"+f"(c[3])
        : "r"(a[0]),"r"(a[1]),"r"(a[2]),"r"(a[3]), "r"(b0),"r"(b1));
}

#define CH 16
#define AST 20
#define ASZ (64*AST)
#define BSZ (384*AST)
#define SMEMB ((2*(ASZ+BSZ))*4)

#define ZACC12(acc) { _Pragma("unroll") for (int i_=0;i_<12;i_++){acc[i_][0]=0.f;acc[i_][1]=0.f;acc[i_][2]=0.f;acc[i_][3]=0.f;} }
#define EPI_IDX5 int rl = wm*32 + mf*16 + (lane>>2) + ((e&2)?8:0); int j = wn*16 + nf*8 + (lane&3)*2 + (e&1);

__device__ __forceinline__ void afrag_load(const uint32_t* As_, uint32_t (*ah)[4], uint32_t (*al)[4],
                                           int lane, int wm){
    const int c0 = (lane&3)*2;
    #pragma unroll
    for (int mf=0; mf<2; mf++){
        int r = wm*32 + mf*16 + (lane>>2);
        uint2 p0 = *(const uint2*)&As_[r*AST + c0];
        uint2 p1 = *(const uint2*)&As_[(r+8)*AST + c0];
        uint2 p2 = *(const uint2*)&As_[r*AST + c0 + 8];
        uint2 p3 = *(const uint2*)&As_[(r+8)*AST + c0 + 8];
        ah[mf][0]=__byte_perm(p0.x,p0.y,0x5410); al[mf][0]=__byte_perm(p0.x,p0.y,0x7632);
        ah[mf][1]=__byte_perm(p1.x,p1.y,0x5410); al[mf][1]=__byte_perm(p1.x,p1.y,0x7632);
        ah[mf][2]=__byte_perm(p2.x,p2.y,0x5410); al[mf][2]=__byte_perm(p2.x,p2.y,0x7632);
        ah[mf][3]=__byte_perm(p3.x,p3.y,0x5410); al[mf][3]=__byte_perm(p3.x,p3.y,0x7632);
    }
}

// 512-thread variant: warp owns 16 N-cols per gate (acc[12][4])
__device__ __forceinline__ void frag_mma12(const uint32_t* As_, const uint32_t* Bs_,
                                           float (*acc)[4], int lane, int wm, int wn){
    const int c0 = (lane&3)*2;
    uint32_t ah[2][4], al[2][4];
    afrag_load(As_, ah, al, lane, wm);
    #pragma unroll
    for (int g=0; g<3; g++)
    #pragma unroll
    for (int nf=0; nf<2; nf++){
        int br = g*128 + wn*16 + nf*8 + (lane>>2);
        uint2 q0 = *(const uint2*)&Bs_[br*AST + c0];
        uint2 q1 = *(const uint2*)&Bs_[br*AST + c0 + 8];
        uint32_t bh0=__byte_perm(q0.x,q0.y,0x5410), bl0=__byte_perm(q0.x,q0.y,0x7632);
        uint32_t bh1=__byte_perm(q1.x,q1.y,0x5410), bl1=__byte_perm(q1.x,q1.y,0x7632);
        #pragma unroll
        for (int mf=0; mf<2; mf++){
            float* ac = acc[(g*2+mf)*2+nf];
            mma_bf16(ac, ah[mf], bh0, bh1);
            mma_bf16(ac, al[mf], bh0, bh1);
            mma_bf16(ac, ah[mf], bl0, bl1);
        }
    }
}

__device__ __forceinline__ void mma_stream512(const uint32_t* Asm, const uint32_t* __restrict__ Bg,
                                              int ldb, int nc, uint32_t* bst, uint32_t sbB,
                                              float (*acc)[4], int tid, int lane, int wm, int wn){
    #define LOADB5(c,s) do{ \
        _Pragma("unroll") \
        for (int i_=0;i_<3;i_++){ int idx=tid+i_*512, rw=idx>>2, sg=idx&3; \
            cpa(sbB + (uint32_t)(((s)*BSZ + rw*AST + sg*4)*4), Bg + (size_t)rw*ldb + (c)*CH + sg*4);} \
        asm volatile("cp.async.commit_group;"); } while(0)
    LOADB5(0,0);
    for (int c=0;c<nc;c++){
        if (c+1<nc){ LOADB5(c+1,(c+1)&1); asm volatile("cp.async.wait_group 1;"); }
        else asm volatile("cp.async.wait_group 0;");
        __syncthreads();
        frag_mma12(Asm + c*ASZ, bst + (c&1)*BSZ, acc, lane, wm, wn);
        __syncthreads();
    }
    #undef LOADB5
}

// EPI=0: gx GEMM (z natural rows, read linear row (q*TT+t); write gx [t][jj][q]).
// EPI=3/4: cheb passes. All 512 threads.
template<int EPI>
__global__ void __launch_bounds__(512) gemm_gru(
    const uint32_t* __restrict__ A, int lda, int K,
    const uint32_t* __restrict__ Bw, int ldb,
    const float* __restrict__ bias, float* __restrict__ C)
{
    extern __shared__ uint32_t smu[];
    const int tid = threadIdx.x, lane = tid & 31, wid = tid >> 5;
    const int wm = wid & 1, wn = wid >> 1;
    const int m0 = blockIdx.x*64, bz = blockIdx.y;
    const int t2 = m0/BN, q0 = m0 - t2*BN;
    if (EPI >= 3){ A += (size_t)bz*LROWS*KC; Bw += (size_t)bz*G3*KC; }
    uint32_t sb = (uint32_t)__cvta_generic_to_shared(smu);
    float acc[12][4]; ZACC12(acc);
    const int nc = K/CH;
    #define LOADC(c,s) do{ \
        if (tid < 256){ \
            int row = tid>>2, seg = tid&3; \
            size_t ar = (EPI==0) ? ((size_t)(q0+row)*TT + t2) : (size_t)(m0+row); \
            cpa(sb + (uint32_t)(((s)*ASZ + row*AST + seg*4)*4), A + ar*lda + (c)*CH + seg*4); \
        } \
        _Pragma("unroll") \
        for (int i_ = 0; i_ < 3; i_++){ \
            int idx = tid + i_*512, rw = idx>>2, sg = idx&3; \
            cpa(sb + (uint32_t)((2*ASZ + (s)*BSZ + rw*AST + sg*4)*4), Bw + (size_t)rw*ldb + (c)*CH + sg*4); \
        } \
        asm volatile("cp.async.commit_group;"); } while(0)
    LOADC(0,0);
    for (int c = 0; c < nc; c++){
        if (c+1 < nc){ LOADC(c+1,(c+1)&1); asm volatile("cp.async.wait_group 1;"); }
        else asm volatile("cp.async.wait_group 0;");
        __syncthreads();
        frag_mma12(smu + (c&1)*ASZ, smu + 2*ASZ + (c&1)*BSZ, acc, lane, wm, wn);
        __syncthreads();
    }
    #undef LOADC
    if (EPI == 0){
        #pragma unroll
        for (int mf=0; mf<2; mf++)
        #pragma unroll
        for (int nf=0; nf<2; nf++)
        #pragma unroll
        for (int e=0; e<4; e++){
            EPI_IDX5; int q = q0 + rl;
            C[((size_t)(t2*G3 + j))*BN + q]       = acc[(0*2+mf)*2+nf][e] + bias[j];
            C[((size_t)(t2*G3 + 128 + j))*BN + q] = acc[(1*2+mf)*2+nf][e] + bias[128+j];
            C[((size_t)(t2*G3 + 256 + j))*BN + q] = acc[(2*2+mf)*2+nf][e] + bias[256+j];
        }
    } else {
        #pragma unroll
        for (int g=0; g<3; g++)
        #pragma unroll
        for (int mf=0; mf<2; mf++)
        #pragma unroll
        for (int nf=0; nf<2; nf++)
        #pragma unroll
        for (int e=0; e<4; e++){
            EPI_IDX5; int grow = m0 + rl;
            if (grow >= NA) continue;
            int jj = g*128 + j;
            float a = acc[(g*2+mf)*2+nf][e];
            size_t off = ((size_t)bz*NA + grow)*G3 + jj;
            if (EPI == 3)
                g_Vt[(size_t)bz*G3*KC + (size_t)jj*KC + grow] = pack_split(g_R1[off] + 2.f*a);
            else
                g_S[off] = fmaxf(a + g_R0[off] - g_R2[off], 0.f);
        }
    }
}

// ---------------- persistent encoder + decoder (512 threads) ----------------
#define HSW 10240
#define CTW 2560
#define BSW (2*BSZ)
#define DGXST 388
#define DGXW (64*DGXST)
#define ED_SMEM_W (HSW + CTW + BSW + DGXW + 384 + 128 + 128 + 128 + 64 + 64)
#define HSI(rl,j) (((j)>>4)*ASZ + (rl)*AST + ((j)&15))

__global__ void __launch_bounds__(512) k_encdec(
    const float* __restrict__ gxp, const float* __restrict__ cemb,
    const float* __restrict__ x, const float* __restrict__ dwih,
    const float* __restrict__ ebhh, const float* __restrict__ dbhh,
    const float* __restrict__ ow, const float* __restrict__ ob,
    float* __restrict__ outp)
{
    extern __shared__ uint32_t S[];
    uint32_t* hs   = S;
    uint32_t* ctxs = S + HSW;
    uint32_t* bst  = S + HSW + CTW;
    float* dgx  = (float*)(S + HSW + CTW + BSW);
    float* wc   = dgx + DGXW;
    float* owl  = wc + 384;
    float* bhne = owl + 128;
    float* bhnd = bhne + 128;
    float* curs = bhnd + 128;
    float* red  = curs + 64;
    uint32_t sbB = (uint32_t)__cvta_generic_to_shared(bst);
    int tid = threadIdx.x, lane = tid & 31, wid = tid >> 5, wm = wid & 1, wn = wid >> 1;
    int m0 = blockIdx.x*64;

    for (int i = tid; i < 384; i += 512) wc[i] = dwih[(size_t)i*33];
    if (tid < 128){ owl[tid] = ow[tid]; bhne[tid] = ebhh[256+tid]; bhnd[tid] = dbhh[256+tid]; }
    for (int i = tid; i < HSW; i += 512) hs[i] = 0u;
    for (int i = tid; i < 64*32; i += 512){
        int rl = i >> 5, k = i & 31, r = m0 + rl, b = r/NA, n = r%NA;
        float v = cemb[(((size_t)b*TT + TT-1)*NA + n)*32 + k];
        ctxs[((k>>4)*64 + rl)*AST + (k&15)] = pack_split(v);
    }
    if (tid < 64){
        int r = m0 + tid, b = r/NA, n = r%NA;
        curs[tid] = x[(((size_t)b*TT + TT-1)*NA + n)*FF];
    }
    __syncthreads();

    float acc[12][4];
    ZACC12(acc);
    mma_stream512(ctxs, g_dwihp, 32, 2, bst, sbB, acc, tid, lane, wm, wn);
    #pragma unroll
    for (int g=0; g<3; g++)
    #pragma unroll
    for (int mf=0; mf<2; mf++)
    #pragma unroll
    for (int nf=0; nf<2; nf++)
    #pragma unroll
    for (int e=0; e<4; e++){
        EPI_IDX5; int jj = g*128 + j;
        dgx[rl*DGXST + jj] = acc[(g*2+mf)*2+nf][e] + g_dbC[jj];
    }
    __syncthreads();

    for (int t = 0; t < TT; t++){
        ZACC12(acc);
        if (t > 0) mma_stream512(hs, g_ewhhp, HID, 8, bst, sbB, acc, tid, lane, wm, wn);
        #pragma unroll
        for (int mf=0; mf<2; mf++)
        #pragma unroll
        for (int nf=0; nf<2; nf++)
        #pragma unroll
        for (int e=0; e<4; e++){
            EPI_IDX5; int grow = m0 + rl;
            float gr = gxp[((size_t)(t*G3 + j))*BN + grow];
            float gz = gxp[((size_t)(t*G3 + 128 + j))*BN + grow];
            float gn = gxp[((size_t)(t*G3 + 256 + j))*BN + grow];
            float rg = sigm(gr + acc[(0*2+mf)*2+nf][e]);
            float zg = sigm(gz + acc[(1*2+mf)*2+nf][e]);
            float ng = tanhf(gn + rg*(acc[(2*2+mf)*2+nf][e] + bhne[j]));
            int hi = HSI(rl, j);
            float hp = unpk(hs[hi]);
            hs[hi] = pack_split((1.f - zg)*ng + zg*hp);
        }
        __syncthreads();
    }

    for (int s = 0; s < HZN; s++){
        ZACC12(acc);
        if (tid < 64) red[tid] = 0.f;
        mma_stream512(hs, g_dwhhp, HID, 8, bst, sbB, acc, tid, lane, wm, wn);
        float pacc[2][2] = {{0.f,0.f},{0.f,0.f}};
        #pragma unroll
        for (int mf=0; mf<2; mf++)
        #pragma unroll
        for (int nf=0; nf<2; nf++)
        #pragma unroll
        for (int e=0; e<4; e++){
            EPI_IDX5;
            float cur = curs[rl];
            float rg = sigm(dgx[rl*DGXST + j]       + cur*wc[j]       + acc[(0*2+mf)*2+nf][e]);
            float zg = sigm(dgx[rl*DGXST + 128 + j] + cur*wc[128+j]   + acc[(1*2+mf)*2+nf][e]);
            float ng = tanhf(dgx[rl*DGXST + 256 + j] + cur*wc[256+j]  + rg*(acc[(2*2+mf)*2+nf][e] + bhnd[j]));
            int hi = HSI(rl, j);
            float hp = unpk(hs[hi]);
            float h2 = (1.f - zg)*ng + zg*hp;
            hs[hi] = pack_split(h2);
            pacc[mf][(e>>1)&1] += h2*owl[j];
        }
        #pragma unroll
        for (int mf=0; mf<2; mf++)
        #pragma unroll
        for (int e2=0; e2<2; e2++)
            atomicAdd(&red[wm*32 + mf*16 + (lane>>2) + e2*8], pacc[mf][e2]);
        __syncthreads();
        if (tid < 64){
            int r = m0 + tid;
            float pr = red[tid] + ob[0];
            curs[tid] = pr;
            outp[(size_t)(r/NA)*(HZN*NA) + (size_t)s*NA + (r%NA)] = pr;
        }
        __syncthreads();
    }
}

// ------------------------------ small kernels -------------------------------
__global__ void k_prep(const float* __restrict__ Ap, const float* __restrict__ alpha){
    __shared__ float red[256];
    float m = -1e30f;
    for (int n = threadIdx.x; n < NA; n += 256){
        float s = 0.f;
        for (int j = 0; j < NA; j++) s += Ap[n*NA+j];
        m = fmaxf(m, s);
    }
    red[threadIdx.x] = m; __syncthreads();
    for (int o = 128; o > 0; o >>= 1){
        if (threadIdx.x < o) red[threadIdx.x] = fmaxf(red[threadIdx.x], red[threadIdx.x+o]);
        __syncthreads();
    }
    if (!threadIdx.x){
        float a = sigm(alpha[0]);
        g_scal[0] = a;
        g_scal[1] = fmaxf(1.f, a*red[0] + 1.f - a);
    }
}

__global__ void k_padw(const float* __restrict__ ewih, const float* __restrict__ ewhh,
                       const float* __restrict__ dwhh, const float* __restrict__ dwih,
                       const float* __restrict__ ebih, const float* __restrict__ ebhh,
                       const float* __restrict__ dbih, const float* __restrict__ dbhh){
    int i = blockIdx.x*blockDim.x + threadIdx.x;
    if (i < G3*ZP){
        int n = i/ZP, k = i%ZP;
        g_wihp[i] = pack_split((k < 65) ? ewih[n*65+k] : 0.f);
        return;
    }
    int j = i - G3*ZP;
    if (j < G3*HID){ g_ewhhp[j] = pack_split(ewhh[j]); return; }
    j -= G3*HID;
    if (j < G3*HID){ g_dwhhp[j] = pack_split(dwhh[j]); return; }
    j -= G3*HID;
    if (j < G3*32){
        int n = j/32, k = j%32;
        g_dwihp[j] = pack_split(dwih[n*33 + 1 + k]);
        return;
    }
    j -= G3*32;
    if (j < G3){ g_bC[j] = ebih[j] + ((j < 256) ? ebhh[j] : 0.f); return; }
    j -= G3;
    if (j < G3){ g_dbC[j] = dbih[j] + ((j < 256) ? dbhh[j] : 0.f); }
}

__global__ void k_emb(const float* __restrict__ x, const float* __restrict__ w,
                      const float* __restrict__ b){
    int i = blockIdx.x*blockDim.x + threadIdx.x;
    if (i >= BN*16) return;
    int j = i & 15, bn = i >> 4, bb = bn/NA, n = bn%NA;
    float s = x[(((size_t)bb*TT + TT-1)*NA + n)*FF];
    g_emb[i] = tanhf(s*w[j] + b[j]);
}

__global__ void k_adyn(){
    __shared__ float se[NA*16];
    int b = blockIdx.x, rt = blockIdx.y;
    for (int i = threadIdx.x; i < NA*16; i += blockDim.x) se[i] = g_emb[b*NA*16+i];
    __syncthreads();
    int m = threadIdx.x;
    if (m >= NA) return;
    float cv[16];
    #pragma unroll
    for (int j = 0; j < 16; j++) cv[j] = se[m*16+j];
    int r0 = rt*32, r1 = (r0+32 < NA) ? r0+32 : NA;
    for (int r = r0; r < r1; r++){
        float s = 0.f;
        #pragma unroll
        for (int j = 0; j < 16; j++) s += se[r*16+j]*cv[j];
        g_L[(size_t)b*NA*NA + (size_t)r*NA + m] = fmaxf(s, 0.f);
    }
}

__global__ void k_topk(const float* __restrict__ Ap){
    int warp = (blockIdx.x*blockDim.x + threadIdx.x) >> 5;
    int lane = threadIdx.x & 31;
    if (warp >= BN) return;
    int b = warp/NA, n = warp%NA;
    const float* row = g_L + (size_t)b*NA*NA + (size_t)n*NA;
    uint32_t* rowp = g_Lp + ((size_t)b*LROWS + n)*KC;
    float v[7], w[7]; int sel = 0;
    #pragma unroll
    for (int s = 0; s < 7; s++){
        int m = s*32 + lane;
        v[s] = (m < NA) ? row[m] : -1e30f;
        w[s] = v[s];
    }
    float topmax = 0.f, sumexp = 0.f;
    for (int it = 0; it < TOPKN; it++){
        float lm = -1e30f; int ls = 0;
        #pragma unroll
        for (int s = 0; s < 7; s++) if (w[s] > lm){ lm = w[s]; ls = s; }
        float gm = lm;
        for (int o = 16; o > 0; o >>= 1) gm = fmaxf(gm, __shfl_xor_sync(~0u, gm, o));
        int my = (lm == gm) ? (ls*32 + lane) : 0x7fffffff;
        int gi = my;
        for (int o = 16; o > 0; o >>= 1) gi = min(gi, __shfl_xor_sync(~0u, gi, o));
        if (!it) topmax = gm;
        sumexp += expf(gm - topmax);
        if ((gi & 31) == lane){ int s = gi >> 5; w[s] = -1e30f; sel |= 1 << s; }
    }
    float e0 = expf(-topmax);
    float inv = 1.f / ((float)(NA-TOPKN)*e0 + sumexp);
    float a = g_scal[0], tol = 2.f/g_scal[1], oma = 1.f - a;
    #pragma unroll
    for (int s = 0; s < 7; s++){
        int m = s*32 + lane;
        if (m < NA){
            float dyn = ((sel >> s) & 1) ? expf(v[s]-topmax)*inv : e0*inv;
            float lv = tol*(a*Ap[n*NA+m] + oma*dyn) - ((m==n) ? 1.f : 0.f);
            rowp[m] = pack_split(lv);
        }
    }
    if (!lane) rowp[NA] = 0u;
}

// fused TCN+GLU+theta: warp per (b,n); lane = feature
__global__ void k_tfr(const float* __restrict__ x, const float* __restrict__ w,
                      const float* __restrict__ wb, const float* __restrict__ th){
    __shared__ float sw[192], sb2[64], sth[3072];
    for (int i = threadIdx.x; i < 192; i += 256) sw[i] = w[i];
    for (int i = threadIdx.x; i < 64; i += 256) sb2[i] = wb[i];
    for (int i = threadIdx.x; i < 3072; i += 256) sth[i] = th[i];
    __syncthreads();
    int warp = (blockIdx.x*256 + threadIdx.x) >> 5;
    int f = threadIdx.x & 31;
    if (warp >= BN) return;
    int b = warp/NA, n = warp%NA;
    const float* xp = x + ((size_t)b*TT*NA + n)*FF;
    float xv = (f < TT) ? xp[(size_t)f*NA*FF] : 0.f;
    float w0p = sw[f*3], w1p = sw[f*3+1], w2p = sw[f*3+2];
    float w0q = sw[(f+32)*3], w1q = sw[(f+32)*3+1], w2q = sw[(f+32)*3+2];
    float bp = sb2[f], bq = sb2[f+32];
    size_t base = (size_t)warp*TT*32;
    #pragma unroll
    for (int t = 0; t < TT; t++){
        float tr0 = (t >= 2) ? __shfl_sync(~0u, xv, t-2) : 0.f;
        float tr1 = (t >= 1) ? __shfl_sync(~0u, xv, t-1) : 0.f;
        float tr2 = __shfl_sync(~0u, xv, t);
        float p = bp + tr0*w0p + tr1*w1p + tr2*w2p;
        float q = bq + tr0*w0q + tr1*w1q + tr2*w2q;
        float tf = p*sigm(q);
        float a0 = 0.f, a1 = 0.f, a2 = 0.f;
        #pragma unroll
        for (int ff = 0; ff < 32; ff++){
            float av = __shfl_sync(~0u, tf, ff);
            a0 += av*sth[ff*32+f];
            a1 += av*sth[1024+ff*32+f];
            a2 += av*sth[2048+ff*32+f];
        }
        g_R0[base + t*32 + f] = a0;
        g_R1[base + t*32 + f] = a1;
        g_R2[base + t*32 + f] = a2;
    }
}

__global__ void k_tr(){
    __shared__ float tile[32][33];
    int b = blockIdx.z, n0 = blockIdx.y*32, j0 = blockIdx.x*32;
    int tx = threadIdx.x & 31, ty = threadIdx.x >> 5;
    #pragma unroll
    for (int i = 0; i < 4; i++){
        int n = n0 + ty + i*8;
        tile[ty+i*8][tx] = (n < NA) ? g_R2[((size_t)b*NA + n)*G3 + j0 + tx] : 0.f;
    }
    __syncthreads();
    #pragma unroll
    for (int i = 0; i < 4; i++){
        int j = j0 + ty + i*8, n = n0 + tx;
        if (n < KC) g_R2t[(size_t)b*G3*KC + (size_t)j*KC + n] = pack_split(tile[tx][ty+i*8]);
    }
}

// fused c_emb + fusion; z written in natural row order
__global__ void k_fusion(const float* __restrict__ x, const float* __restrict__ aw,
                         const float* __restrict__ ab, const float* __restrict__ cw,
                         const float* __restrict__ cb){
    __shared__ float sw[416], sb2[32], sa[65];
    for (int i = threadIdx.x; i < 416; i += blockDim.x) sw[i] = cw[i];
    for (int i = threadIdx.x; i < 32; i += blockDim.x) sb2[i] = cb[i];
    for (int i = threadIdx.x; i < 65; i += blockDim.x) sa[i] = aw[i];
    __syncthreads();
    int g = (blockIdx.x*blockDim.x + threadIdx.x) >> 5;
    int lane = threadIdx.x & 31;
    if (g >= BTN) return;
    int b = g/(TT*NA), rem = g - b*TT*NA, t = rem/NA, n = rem - t*NA;
    int bn = b*NA + n;
    const float* sf = g_S + (size_t)bn*G3 + t*32;
    const float* xin = x + (size_t)g*FF;
    float s = sb2[lane];
    #pragma unroll
    for (int f = 0; f < 13; f++) s += xin[1+f]*sw[lane*13+f];
    float ce = fmaxf(s, 0.f);
    float cem1 = __shfl_up_sync(~0u, ce, 1);
    float ce31 = __shfl_sync(~0u, ce, 31);
    float v0 = lane ? sf[lane-1] : xin[0];
    float v1 = lane ? cem1 : sf[31];
    float v2 = lane ? 0.f : ce31;
    float dot = v0*sa[lane] + v1*sa[32+lane] + (lane ? 0.f : v2*sa[64]);
    for (int o = 16; o > 0; o >>= 1) dot += __shfl_xor_sync(~0u, dot, o);
    float attn = sigm(dot + ab[0]);
    uint32_t* zr = g_z + (size_t)g*ZP;
    zr[lane]    = pack_split(v0*attn);
    zr[32+lane] = pack_split(v1*attn);
    zr[64+lane] = lane ? 0u : pack_split(v2*attn);
    if (t == TT-1) g_cemb[(size_t)g*32 + lane] = ce;
}

extern "C" void kernel_launch(void* const* d_in, const int* in_sizes, int n_in,
                              void* d_out, int out_size){
    const float* x = (const float*)d_in[0];
    const float* Ap = (const float*)d_in[1];
    const float* fcw = (const float*)d_in[2];
    const float* fcb = (const float*)d_in[3];
    const float* alpha = (const float*)d_in[4];
    const float* cw = (const float*)d_in[5];
    const float* cb = (const float*)d_in[6];
    const float* tw = (const float*)d_in[7];
    const float* tb = (const float*)d_in[8];
    const float* theta = (const float*)d_in[9];
    const float* aw = (const float*)d_in[10];
    const float* ab = (const float*)d_in[11];
    const float* ewih = (const float*)d_in[12];
    const float* ewhh = (const float*)d_in[13];
    const float* ebih = (const float*)d_in[14];
    const float* ebhh = (const float*)d_in[15];
    const float* dwih = (const float*)d_in[16];
    const float* dwhh = (const float*)d_in[17];
    const float* dbih = (const float*)d_in[18];
    const float* dbhh = (const float*)d_in[19];
    const float* ow = (const float*)d_in[20];
    const float* ob = (const float*)d_in[21];
    float* out = (float*)d_out;
    (void)in_sizes; (void)n_in; (void)out_size;

    cudaFuncSetAttribute(gemm_gru<0>, cudaFuncAttributeMaxDynamicSharedMemorySize, SMEMB);
    cudaFuncSetAttribute(gemm_gru<3>, cudaFuncAttributeMaxDynamicSharedMemorySize, SMEMB);
    cudaFuncSetAttribute(gemm_gru<4>, cudaFuncAttributeMaxDynamicSharedMemorySize, SMEMB);
    cudaFuncSetAttribute(k_encdec, cudaFuncAttributeMaxDynamicSharedMemorySize, ED_SMEM_W*4);

    float *pGX, *pCemb, *pbC;
    uint32_t *pZ, *pWih, *pLp, *pR2t, *pVt;
    cudaGetSymbolAddress((void**)&pGX, g_gx);
    cudaGetSymbolAddress((void**)&pZ, g_z);
    cudaGetSymbolAddress((void**)&pWih, g_wihp);
    cudaGetSymbolAddress((void**)&pLp, g_Lp);
    cudaGetSymbolAddress((void**)&pR2t, g_R2t);
    cudaGetSymbolAddress((void**)&pVt, g_Vt);
    cudaGetSymbolAddress((void**)&pCemb, g_cemb);
    cudaGetSymbolAddress((void**)&pbC, g_bC);

    k_prep<<<1,256>>>(Ap, alpha);
    k_padw<<<(G3*ZP + 2*G3*HID + G3*32 + 2*G3 + 255)/256,256>>>(ewih, ewhh, dwhh, dwih, ebih, ebhh, dbih, dbhh);
    k_emb<<<(BN*16+255)/256,256>>>(x, fcw, fcb);
    k_adyn<<<dim3(BB,7),256>>>();
    k_topk<<<(BN+7)/8,256>>>(Ap);

    k_tfr<<<(BN*32+255)/256,256>>>(x, tw, tb, theta);
    k_tr<<<dim3(G3/32, (NA+31)/32, BB),256>>>();
    gemm_gru<3><<<dim3(4,BB),512,SMEMB>>>(pLp, KC, KC, pR2t, KC, nullptr, nullptr);
    gemm_gru<4><<<dim3(4,BB),512,SMEMB>>>(pLp, KC, KC, pVt, KC, nullptr, nullptr);

    k_fusion<<<(BTN*32+255)/256,256>>>(x, aw, ab, cw, cb);

    gemm_gru<0><<<BTN/64,512,SMEMB>>>(pZ, ZP, ZP, pWih, ZP, pbC, pGX);
    k_encdec<<<BN/64,512,ED_SMEM_W*4>>>(pGX, pCemb, x, dwih, ebhh, dbhh, ow, ob, out);
}

// round 17
// speedup vs baseline: 1.0547x; 1.0547x over previous
#include <cuda_runtime.h>
#include <cuda_bf16.h>
#include <stdint.h>
#include <math.h>

#define BB 128
#define TT 12
#define NA 207
#define FF 14
#define HID 128
#define G3 384
#define TOPKN 10
#define HZN 12
#define BN (BB*NA)
#define BTN (BB*TT*NA)
#define ZP 96
#define KC 208
#define LROWS 256

__device__ float    g_emb[BN*16];
__device__ float    g_L[(size_t)BB*NA*NA];
__device__ uint32_t g_Lp[(size_t)BB*LROWS*KC];
__device__ float    g_R0[(size_t)BN*G3];
__device__ float    g_R1[(size_t)BN*G3];
__device__ float    g_R2[(size_t)BN*G3];
__device__ uint32_t g_R2t[(size_t)BB*G3*KC];
__device__ uint32_t g_Vt[(size_t)BB*G3*KC];
__device__ float    g_S[(size_t)BN*G3];
__device__ float    g_cemb[(size_t)BTN*32];
__device__ uint32_t g_z[(size_t)BTN*ZP];
__device__ float    g_gx[(size_t)BTN*G3];
__device__ float    g_scal[2];
__device__ uint32_t g_wihp[G3*ZP];
__device__ uint32_t g_ewhhp[G3*HID];
__device__ uint32_t g_dwhhp[G3*HID];
__device__ uint32_t g_dwihp[G3*32];
__device__ float    g_bC[G3];
__device__ float    g_dbC[G3];

__device__ __forceinline__ float sigm(float x){
    return __fdividef(1.f, 1.f + __expf(-x));
}
__device__ __forceinline__ float ftanh(float x){
    return 1.f - __fdividef(2.f, __expf(2.f*x) + 1.f);
}
__device__ __forceinline__ uint32_t pack_split(float x){
    __nv_bfloat16 h = __float2bfloat16(x);
    float hr = __bfloat162float(h);
    __nv_bfloat16 l = __float2bfloat16(x - hr);
    return (uint32_t)__bfloat16_as_ushort(h) | ((uint32_t)__bfloat16_as_ushort(l) << 16);
}
__device__ __forceinline__ float unpk(uint32_t p){
    return __bfloat162float(__ushort_as_bfloat16((unsigned short)(p & 0xffffu)))
         + __bfloat162float(__ushort_as_bfloat16((unsigned short)(p >> 16)));
}
__device__ __forceinline__ void cpa(uint32_t dst, const void* src){
    asm volatile("cp.async.cg.shared.global [%0], [%1], 16;" :: "r"(dst), "l"(src));
}
__device__ __forceinline__ void mma_bf16(float* c, const uint32_t* a, uint32_t b0, uint32_t b1){
    asm volatile("mma.sync.aligned.m16n8k16.row.col.f32.bf16.bf16.f32 "
        "{%0,%1,%2,%3}, {%4,%5,%6,%7}, {%8,%9}, {%0,%1,%2,%3};"
        : "+f"(c[0]),"+f"(c[1]),"+f"(c[2]),"+f"(c[3])
        : "r"(a[0]),"r"(a[1]),"r"(a[2]),"r"(a[3]), "r"(b0),"r"(b1));
}

#define CH 16
#define AST 20
#define ASZ (64*AST)
#define BSZ (384*AST)
#define SMEMB ((2*(ASZ+BSZ))*4)

#define ZACC12(acc) { _Pragma("unroll") for (int i_=0;i_<12;i_++){acc[i_][0]=0.f;acc[i_][1]=0.f;acc[i_][2]=0.f;acc[i_][3]=0.f;} }
#define EPI_IDX5 int rl = wm*32 + mf*16 + (lane>>2) + ((e&2)?8:0); int j = wn*16 + nf*8 + (lane&3)*2 + (e&1);

__device__ __forceinline__ void afrag_load(const uint32_t* As_, uint32_t (*ah)[4], uint32_t (*al)[4],
                                           int lane, int wm){
    const int c0 = (lane&3)*2;
    #pragma unroll
    for (int mf=0; mf<2; mf++){
        int r = wm*32 + mf*16 + (lane>>2);
        uint2 p0 = *(const uint2*)&As_[r*AST + c0];
        uint2 p1 = *(const uint2*)&As_[(r+8)*AST + c0];
        uint2 p2 = *(const uint2*)&As_[r*AST + c0 + 8];
        uint2 p3 = *(const uint2*)&As_[(r+8)*AST + c0 + 8];
        ah[mf][0]=__byte_perm(p0.x,p0.y,0x5410); al[mf][0]=__byte_perm(p0.x,p0.y,0x7632);
        ah[mf][1]=__byte_perm(p1.x,p1.y,0x5410); al[mf][1]=__byte_perm(p1.x,p1.y,0x7632);
        ah[mf][2]=__byte_perm(p2.x,p2.y,0x5410); al[mf][2]=__byte_perm(p2.x,p2.y,0x7632);
        ah[mf][3]=__byte_perm(p3.x,p3.y,0x5410); al[mf][3]=__byte_perm(p3.x,p3.y,0x7632);
    }
}

__device__ __forceinline__ void frag_mma12(const uint32_t* As_, const uint32_t* Bs_,
                                           float (*acc)[4], int lane, int wm, int wn){
    const int c0 = (lane&3)*2;
    uint32_t ah[2][4], al[2][4];
    afrag_load(As_, ah, al, lane, wm);
    #pragma unroll
    for (int g=0; g<3; g++)
    #pragma unroll
    for (int nf=0; nf<2; nf++){
        int br = g*128 + wn*16 + nf*8 + (lane>>2);
        uint2 q0 = *(const uint2*)&Bs_[br*AST + c0];
        uint2 q1 = *(const uint2*)&Bs_[br*AST + c0 + 8];
        uint32_t bh0=__byte_perm(q0.x,q0.y,0x5410), bl0=__byte_perm(q0.x,q0.y,0x7632);
        uint32_t bh1=__byte_perm(q1.x,q1.y,0x5410), bl1=__byte_perm(q1.x,q1.y,0x7632);
        #pragma unroll
        for (int mf=0; mf<2; mf++){
            float* ac = acc[(g*2+mf)*2+nf];
            mma_bf16(ac, ah[mf], bh0, bh1);
            mma_bf16(ac, al[mf], bh0, bh1);
            mma_bf16(ac, ah[mf], bl0, bl1);
        }
    }
}

__device__ __forceinline__ void mma_stream512(const uint32_t* Asm, const uint32_t* __restrict__ Bg,
                                              int ldb, int nc, uint32_t* bst, uint32_t sbB,
                                              float (*acc)[4], int tid, int lane, int wm, int wn){
    #define LOADB5(c,s) do{ \
        _Pragma("unroll") \
        for (int i_=0;i_<3;i_++){ int idx=tid+i_*512, rw=idx>>2, sg=idx&3; \
            cpa(sbB + (uint32_t)(((s)*BSZ + rw*AST + sg*4)*4), Bg + (size_t)rw*ldb + (c)*CH + sg*4);} \
        asm volatile("cp.async.commit_group;"); } while(0)
    LOADB5(0,0);
    for (int c=0;c<nc;c++){
        if (c+1<nc){ LOADB5(c+1,(c+1)&1); asm volatile("cp.async.wait_group 1;"); }
        else asm volatile("cp.async.wait_group 0;");
        __syncthreads();
        frag_mma12(Asm + c*ASZ, bst + (c&1)*BSZ, acc, lane, wm, wn);
        __syncthreads();
    }
    #undef LOADB5
}

// EPI=0: gx GEMM. EPI=3/4: cheb passes. 512 threads.
template<int EPI>
__global__ void __launch_bounds__(512) gemm_gru(
    const uint32_t* __restrict__ A, int lda, int K,
    const uint32_t* __restrict__ Bw, int ldb,
    const float* __restrict__ bias, float* __restrict__ C)
{
    extern __shared__ uint32_t smu[];
    const int tid = threadIdx.x, lane = tid & 31, wid = tid >> 5;
    const int wm = wid & 1, wn = wid >> 1;
    const int m0 = blockIdx.x*64, bz = blockIdx.y;
    const int t2 = m0/BN, q0 = m0 - t2*BN;
    if (EPI >= 3){ A += (size_t)bz*LROWS*KC; Bw += (size_t)bz*G3*KC; }
    uint32_t sb = (uint32_t)__cvta_generic_to_shared(smu);
    float acc[12][4]; ZACC12(acc);
    const int nc = K/CH;
    #define LOADC(c,s) do{ \
        if (tid < 256){ \
            int row = tid>>2, seg = tid&3; \
            size_t ar = (EPI==0) ? ((size_t)(q0+row)*TT + t2) : (size_t)(m0+row); \
            cpa(sb + (uint32_t)(((s)*ASZ + row*AST + seg*4)*4), A + ar*lda + (c)*CH + seg*4); \
        } \
        _Pragma("unroll") \
        for (int i_ = 0; i_ < 3; i_++){ \
            int idx = tid + i_*512, rw = idx>>2, sg = idx&3; \
            cpa(sb + (uint32_t)((2*ASZ + (s)*BSZ + rw*AST + sg*4)*4), Bw + (size_t)rw*ldb + (c)*CH + sg*4); \
        } \
        asm volatile("cp.async.commit_group;"); } while(0)
    LOADC(0,0);
    for (int c = 0; c < nc; c++){
        if (c+1 < nc){ LOADC(c+1,(c+1)&1); asm volatile("cp.async.wait_group 1;"); }
        else asm volatile("cp.async.wait_group 0;");
        __syncthreads();
        frag_mma12(smu + (c&1)*ASZ, smu + 2*ASZ + (c&1)*BSZ, acc, lane, wm, wn);
        __syncthreads();
    }
    #undef LOADC
    if (EPI == 0){
        #pragma unroll
        for (int mf=0; mf<2; mf++)
        #pragma unroll
        for (int nf=0; nf<2; nf++)
        #pragma unroll
        for (int e=0; e<4; e++){
            EPI_IDX5; int q = q0 + rl;
            C[((size_t)(t2*G3 + j))*BN + q]       = acc[(0*2+mf)*2+nf][e] + bias[j];
            C[((size_t)(t2*G3 + 128 + j))*BN + q] = acc[(1*2+mf)*2+nf][e] + bias[128+j];
            C[((size_t)(t2*G3 + 256 + j))*BN + q] = acc[(2*2+mf)*2+nf][e] + bias[256+j];
        }
    } else {
        #pragma unroll
        for (int g=0; g<3; g++)
        #pragma unroll
        for (int mf=0; mf<2; mf++)
        #pragma unroll
        for (int nf=0; nf<2; nf++)
        #pragma unroll
        for (int e=0; e<4; e++){
            EPI_IDX5; int grow = m0 + rl;
            if (grow >= NA) continue;
            int jj = g*128 + j;
            float a = acc[(g*2+mf)*2+nf][e];
            size_t off = ((size_t)bz*NA + grow)*G3 + jj;
            if (EPI == 3)
                g_Vt[(size_t)bz*G3*KC + (size_t)jj*KC + grow] = pack_split(g_R1[off] + 2.f*a);
            else
                g_S[off] = fmaxf(a + g_R0[off] - g_R2[off], 0.f);
        }
    }
}

// ---------------- persistent encoder + decoder (512 threads) ----------------
#define HSW 10240
#define CTW 2560
#define BSW (2*BSZ)
#define DGXST 388
#define DGXW (64*DGXST)
#define ED_SMEM_W (HSW + CTW + BSW + DGXW + 384 + 128 + 128 + 128 + 64 + 64)
#define HSI(rl,j) (((j)>>4)*ASZ + (rl)*AST + ((j)&15))

__global__ void __launch_bounds__(512) k_encdec(
    const float* __restrict__ gxp, const float* __restrict__ cemb,
    const float* __restrict__ x, const float* __restrict__ dwih,
    const float* __restrict__ ebhh, const float* __restrict__ dbhh,
    const float* __restrict__ ow, const float* __restrict__ ob,
    float* __restrict__ outp)
{
    extern __shared__ uint32_t S[];
    uint32_t* hs   = S;
    uint32_t* ctxs = S + HSW;
    uint32_t* bst  = S + HSW + CTW;
    float* dgx  = (float*)(S + HSW + CTW + BSW);
    float* wc   = dgx + DGXW;
    float* owl  = wc + 384;
    float* bhne = owl + 128;
    float* bhnd = bhne + 128;
    float* curs = bhnd + 128;
    float* red  = curs + 64;
    uint32_t sbB = (uint32_t)__cvta_generic_to_shared(bst);
    int tid = threadIdx.x, lane = tid & 31, wid = tid >> 5, wm = wid & 1, wn = wid >> 1;
    int m0 = blockIdx.x*64;

    for (int i = tid; i < 384; i += 512) wc[i] = dwih[(size_t)i*33];
    if (tid < 128){ owl[tid] = ow[tid]; bhne[tid] = ebhh[256+tid]; bhnd[tid] = dbhh[256+tid]; }
    for (int i = tid; i < HSW; i += 512) hs[i] = 0u;
    for (int i = tid; i < 64*32; i += 512){
        int rl = i >> 5, k = i & 31, r = m0 + rl, b = r/NA, n = r%NA;
        float v = cemb[(((size_t)b*TT + TT-1)*NA + n)*32 + k];
        ctxs[((k>>4)*64 + rl)*AST + (k&15)] = pack_split(v);
    }
    if (tid < 64){
        int r = m0 + tid, b = r/NA, n = r%NA;
        curs[tid] = x[(((size_t)b*TT + TT-1)*NA + n)*FF];
    }
    __syncthreads();

    float acc[12][4];
    ZACC12(acc);
    mma_stream512(ctxs, g_dwihp, 32, 2, bst, sbB, acc, tid, lane, wm, wn);
    #pragma unroll
    for (int g=0; g<3; g++)
    #pragma unroll
    for (int mf=0; mf<2; mf++)
    #pragma unroll
    for (int nf=0; nf<2; nf++)
    #pragma unroll
    for (int e=0; e<4; e++){
        EPI_IDX5; int jj = g*128 + j;
        dgx[rl*DGXST + jj] = acc[(g*2+mf)*2+nf][e] + g_dbC[jj];
    }
    __syncthreads();

    for (int t = 0; t < TT; t++){
        ZACC12(acc);
        if (t > 0) mma_stream512(hs, g_ewhhp, HID, 8, bst, sbB, acc, tid, lane, wm, wn);
        #pragma unroll
        for (int mf=0; mf<2; mf++)
        #pragma unroll
        for (int nf=0; nf<2; nf++)
        #pragma unroll
        for (int e=0; e<4; e++){
            EPI_IDX5; int grow = m0 + rl;
            float gr = gxp[((size_t)(t*G3 + j))*BN + grow];
            float gz = gxp[((size_t)(t*G3 + 128 + j))*BN + grow];
            float gn = gxp[((size_t)(t*G3 + 256 + j))*BN + grow];
            float rg = sigm(gr + acc[(0*2+mf)*2+nf][e]);
            float zg = sigm(gz + acc[(1*2+mf)*2+nf][e]);
            float ng = ftanh(gn + rg*(acc[(2*2+mf)*2+nf][e] + bhne[j]));
            int hi = HSI(rl, j);
            float hp = unpk(hs[hi]);
            hs[hi] = pack_split((1.f - zg)*ng + zg*hp);
        }
        __syncthreads();
    }

    for (int s = 0; s < HZN; s++){
        ZACC12(acc);
        if (tid < 64) red[tid] = 0.f;
        mma_stream512(hs, g_dwhhp, HID, 8, bst, sbB, acc, tid, lane, wm, wn);
        float pacc[2][2] = {{0.f,0.f},{0.f,0.f}};
        #pragma unroll
        for (int mf=0; mf<2; mf++)
        #pragma unroll
        for (int nf=0; nf<2; nf++)
        #pragma unroll
        for (int e=0; e<4; e++){
            EPI_IDX5;
            float cur = curs[rl];
            float rg = sigm(dgx[rl*DGXST + j]       + cur*wc[j]       + acc[(0*2+mf)*2+nf][e]);
            float zg = sigm(dgx[rl*DGXST + 128 + j] + cur*wc[128+j]   + acc[(1*2+mf)*2+nf][e]);
            float ng = ftanh(dgx[rl*DGXST + 256 + j] + cur*wc[256+j]  + rg*(acc[(2*2+mf)*2+nf][e] + bhnd[j]));
            int hi = HSI(rl, j);
            float hp = unpk(hs[hi]);
            float h2 = (1.f - zg)*ng + zg*hp;
            hs[hi] = pack_split(h2);
            pacc[mf][(e>>1)&1] += h2*owl[j];
        }
        #pragma unroll
        for (int mf=0; mf<2; mf++)
        #pragma unroll
        for (int e2=0; e2<2; e2++)
            atomicAdd(&red[wm*32 + mf*16 + (lane>>2) + e2*8], pacc[mf][e2]);
        __syncthreads();
        if (tid < 64){
            int r = m0 + tid;
            float pr = red[tid] + ob[0];
            curs[tid] = pr;
            outp[(size_t)(r/NA)*(HZN*NA) + (size_t)s*NA + (r%NA)] = pr;
        }
        __syncthreads();
    }
}

// ------------------------------ small kernels -------------------------------
__global__ void k_prep(const float* __restrict__ Ap, const float* __restrict__ alpha){
    __shared__ float red[256];
    float m = -1e30f;
    for (int n = threadIdx.x; n < NA; n += 256){
        float s = 0.f;
        for (int j = 0; j < NA; j++) s += Ap[n*NA+j];
        m = fmaxf(m, s);
    }
    red[threadIdx.x] = m; __syncthreads();
    for (int o = 128; o > 0; o >>= 1){
        if (threadIdx.x < o) red[threadIdx.x] = fmaxf(red[threadIdx.x], red[threadIdx.x+o]);
        __syncthreads();
    }
    if (!threadIdx.x){
        float a = 1.f/(1.f+expf(-alpha[0]));
        g_scal[0] = a;
        g_scal[1] = fmaxf(1.f, a*red[0] + 1.f - a);
    }
}

__global__ void k_padw(const float* __restrict__ ewih, const float* __restrict__ ewhh,
                       const float* __restrict__ dwhh, const float* __restrict__ dwih,
                       const float* __restrict__ ebih, const float* __restrict__ ebhh,
                       const float* __restrict__ dbih, const float* __restrict__ dbhh){
    int i = blockIdx.x*blockDim.x + threadIdx.x;
    if (i < G3*ZP){
        int n = i/ZP, k = i%ZP;
        g_wihp[i] = pack_split((k < 65) ? ewih[n*65+k] : 0.f);
        return;
    }
    int j = i - G3*ZP;
    if (j < G3*HID){ g_ewhhp[j] = pack_split(ewhh[j]); return; }
    j -= G3*HID;
    if (j < G3*HID){ g_dwhhp[j] = pack_split(dwhh[j]); return; }
    j -= G3*HID;
    if (j < G3*32){
        int n = j/32, k = j%32;
        g_dwihp[j] = pack_split(dwih[n*33 + 1 + k]);
        return;
    }
    j -= G3*32;
    if (j < G3){ g_bC[j] = ebih[j] + ((j < 256) ? ebhh[j] : 0.f); return; }
    j -= G3;
    if (j < G3){ g_dbC[j] = dbih[j] + ((j < 256) ? dbhh[j] : 0.f); }
}

__global__ void k_emb(const float* __restrict__ x, const float* __restrict__ w,
                      const float* __restrict__ b){
    int i = blockIdx.x*blockDim.x + threadIdx.x;
    if (i >= BN*16) return;
    int j = i & 15, bn = i >> 4, bb = bn/NA, n = bn%NA;
    float s = x[(((size_t)bb*TT + TT-1)*NA + n)*FF];
    g_emb[i] = tanhf(s*w[j] + b[j]);
}

__global__ void k_adyn(){
    __shared__ float se[NA*16];
    int b = blockIdx.x, rt = blockIdx.y;
    for (int i = threadIdx.x; i < NA*16; i += blockDim.x) se[i] = g_emb[b*NA*16+i];
    __syncthreads();
    int m = threadIdx.x;
    if (m >= NA) return;
    float cv[16];
    #pragma unroll
    for (int j = 0; j < 16; j++) cv[j] = se[m*16+j];
    int r0 = rt*32, r1 = (r0+32 < NA) ? r0+32 : NA;
    for (int r = r0; r < r1; r++){
        float s = 0.f;
        #pragma unroll
        for (int j = 0; j < 16; j++) s += se[r*16+j]*cv[j];
        g_L[(size_t)b*NA*NA + (size_t)r*NA + m] = fmaxf(s, 0.f);
    }
}

__global__ void k_topk(const float* __restrict__ Ap){
    int warp = (blockIdx.x*blockDim.x + threadIdx.x) >> 5;
    int lane = threadIdx.x & 31;
    if (warp >= BN) return;
    int b = warp/NA, n = warp%NA;
    const float* row = g_L + (size_t)b*NA*NA + (size_t)n*NA;
    uint32_t* rowp = g_Lp + ((size_t)b*LROWS + n)*KC;
    float v[7], w[7]; int sel = 0;
    #pragma unroll
    for (int s = 0; s < 7; s++){
        int m = s*32 + lane;
        v[s] = (m < NA) ? row[m] : -1e30f;
        w[s] = v[s];
    }
    float topmax = 0.f, sumexp = 0.f;
    for (int it = 0; it < TOPKN; it++){
        float lm = -1e30f; int ls = 0;
        #pragma unroll
        for (int s = 0; s < 7; s++) if (w[s] > lm){ lm = w[s]; ls = s; }
        float gm = lm;
        for (int o = 16; o > 0; o >>= 1) gm = fmaxf(gm, __shfl_xor_sync(~0u, gm, o));
        int my = (lm == gm) ? (ls*32 + lane) : 0x7fffffff;
        int gi = my;
        for (int o = 16; o > 0; o >>= 1) gi = min(gi, __shfl_xor_sync(~0u, gi, o));
        if (!it) topmax = gm;
        sumexp += expf(gm - topmax);
        if ((gi & 31) == lane){ int s = gi >> 5; w[s] = -1e30f; sel |= 1 << s; }
    }
    float e0 = expf(-topmax);
    float inv = 1.f / ((float)(NA-TOPKN)*e0 + sumexp);
    float a = g_scal[0], tol = 2.f/g_scal[1], oma = 1.f - a;
    #pragma unroll
    for (int s = 0; s < 7; s++){
        int m = s*32 + lane;
        if (m < NA){
            float dyn = ((sel >> s) & 1) ? expf(v[s]-topmax)*inv : e0*inv;
            float lv = tol*(a*Ap[n*NA+m] + oma*dyn) - ((m==n) ? 1.f : 0.f);
            rowp[m] = pack_split(lv);
        }
    }
    if (!lane) rowp[NA] = 0u;
}

// fused TCN+GLU+theta: warp per (b,n); lane = feature
__global__ void k_tfr(const float* __restrict__ x, const float* __restrict__ w,
                      const float* __restrict__ wb, const float* __restrict__ th){
    __shared__ float sw[192], sb2[64], sth[3072];
    for (int i = threadIdx.x; i < 192; i += 256) sw[i] = w[i];
    for (int i = threadIdx.x; i < 64; i += 256) sb2[i] = wb[i];
    for (int i = threadIdx.x; i < 3072; i += 256) sth[i] = th[i];
    __syncthreads();
    int warp = (blockIdx.x*256 + threadIdx.x) >> 5;
    int f = threadIdx.x & 31;
    if (warp >= BN) return;
    int b = warp/NA, n = warp%NA;
    const float* xp = x + ((size_t)b*TT*NA + n)*FF;
    float xv = (f < TT) ? xp[(size_t)f*NA*FF] : 0.f;
    float w0p = sw[f*3], w1p = sw[f*3+1], w2p = sw[f*3+2];
    float w0q = sw[(f+32)*3], w1q = sw[(f+32)*3+1], w2q = sw[(f+32)*3+2];
    float bp = sb2[f], bq = sb2[f+32];
    size_t base = (size_t)warp*TT*32;
    #pragma unroll
    for (int t = 0; t < TT; t++){
        float tr0 = (t >= 2) ? __shfl_sync(~0u, xv, t-2) : 0.f;
        float tr1 = (t >= 1) ? __shfl_sync(~0u, xv, t-1) : 0.f;
        float tr2 = __shfl_sync(~0u, xv, t);
        float p = bp + tr0*w0p + tr1*w1p + tr2*w2p;
        float q = bq + tr0*w0q + tr1*w1q + tr2*w2q;
        float tf = p*sigm(q);
        float a0 = 0.f, a1 = 0.f, a2 = 0.f;
        #pragma unroll
        for (int ff = 0; ff < 32; ff++){
            float av = __shfl_sync(~0u, tf, ff);
            a0 += av*sth[ff*32+f];
            a1 += av*sth[1024+ff*32+f];
            a2 += av*sth[2048+ff*32+f];
        }
        g_R0[base + t*32 + f] = a0;
        g_R1[base + t*32 + f] = a1;
        g_R2[base + t*32 + f] = a2;
    }
}

__global__ void k_tr(){
    __shared__ float tile[32][33];
    int b = blockIdx.z, n0 = blockIdx.y*32, j0 = blockIdx.x*32;
    int tx = threadIdx.x & 31, ty = threadIdx.x >> 5;
    #pragma unroll
    for (int i = 0; i < 4; i++){
        int n = n0 + ty + i*8;
        tile[ty+i*8][tx] = (n < NA) ? g_R2[((size_t)b*NA + n)*G3 + j0 + tx] : 0.f;
    }
    __syncthreads();
    #pragma unroll
    for (int i = 0; i < 4; i++){
        int j = j0 + ty + i*8, n = n0 + tx;
        if (n < KC) g_R2t[(size_t)b*G3*KC + (size_t)j*KC + n] = pack_split(tile[tx][ty+i*8]);
    }
}

// fused c_emb + fusion; z written in natural row order
__global__ void k_fusion(const float* __restrict__ x, const float* __restrict__ aw,
                         const float* __restrict__ ab, const float* __restrict__ cw,
                         const float* __restrict__ cb){
    __shared__ float sw[416], sb2[32], sa[65];
    for (int i = threadIdx.x; i < 416; i += blockDim.x) sw[i] = cw[i];
    for (int i = threadIdx.x; i < 32; i += blockDim.x) sb2[i] = cb[i];
    for (int i = threadIdx.x; i < 65; i += blockDim.x) sa[i] = aw[i];
    __syncthreads();
    int g = (blockIdx.x*blockDim.x + threadIdx.x) >> 5;
    int lane = threadIdx.x & 31;
    if (g >= BTN) return;
    int b = g/(TT*NA), rem = g - b*TT*NA, t = rem/NA, n = rem - t*NA;
    int bn = b*NA + n;
    const float* sf = g_S + (size_t)bn*G3 + t*32;
    const float* xin = x + (size_t)g*FF;
    float s = sb2[lane];
    #pragma unroll
    for (int f = 0; f < 13; f++) s += xin[1+f]*sw[lane*13+f];
    float ce = fmaxf(s, 0.f);
    float cem1 = __shfl_up_sync(~0u, ce, 1);
    float ce31 = __shfl_sync(~0u, ce, 31);
    float v0 = lane ? sf[lane-1] : xin[0];
    float v1 = lane ? cem1 : sf[31];
    float v2 = lane ? 0.f : ce31;
    float dot = v0*sa[lane] + v1*sa[32+lane] + (lane ? 0.f : v2*sa[64]);
    for (int o = 16; o > 0; o >>= 1) dot += __shfl_xor_sync(~0u, dot, o);
    float attn = sigm(dot + ab[0]);
    uint32_t* zr = g_z + (size_t)g*ZP;
    zr[lane]    = pack_split(v0*attn);
    zr[32+lane] = pack_split(v1*attn);
    zr[64+lane] = lane ? 0u : pack_split(v2*attn);
    if (t == TT-1) g_cemb[(size_t)g*32 + lane] = ce;
}

extern "C" void kernel_launch(void* const* d_in, const int* in_sizes, int n_in,
                              void* d_out, int out_size){
    const float* x = (const float*)d_in[0];
    const float* Ap = (const float*)d_in[1];
    const float* fcw = (const float*)d_in[2];
    const float* fcb = (const float*)d_in[3];
    const float* alpha = (const float*)d_in[4];
    const float* cw = (const float*)d_in[5];
    const float* cb = (const float*)d_in[6];
    const float* tw = (const float*)d_in[7];
    const float* tb = (const float*)d_in[8];
    const float* theta = (const float*)d_in[9];
    const float* aw = (const float*)d_in[10];
    const float* ab = (const float*)d_in[11];
    const float* ewih = (const float*)d_in[12];
    const float* ewhh = (const float*)d_in[13];
    const float* ebih = (const float*)d_in[14];
    const float* ebhh = (const float*)d_in[15];
    const float* dwih = (const float*)d_in[16];
    const float* dwhh = (const float*)d_in[17];
    const float* dbih = (const float*)d_in[18];
    const float* dbhh = (const float*)d_in[19];
    const float* ow = (const float*)d_in[20];
    const float* ob = (const float*)d_in[21];
    float* out = (float*)d_out;
    (void)in_sizes; (void)n_in; (void)out_size;

    cudaFuncSetAttribute(gemm_gru<0>, cudaFuncAttributeMaxDynamicSharedMemorySize, SMEMB);
    cudaFuncSetAttribute(gemm_gru<3>, cudaFuncAttributeMaxDynamicSharedMemorySize, SMEMB);
    cudaFuncSetAttribute(gemm_gru<4>, cudaFuncAttributeMaxDynamicSharedMemorySize, SMEMB);
    cudaFuncSetAttribute(k_encdec, cudaFuncAttributeMaxDynamicSharedMemorySize, ED_SMEM_W*4);

    float *pGX, *pCemb, *pbC;
    uint32_t *pZ, *pWih, *pLp, *pR2t, *pVt;
    cudaGetSymbolAddress((void**)&pGX, g_gx);
    cudaGetSymbolAddress((void**)&pZ, g_z);
    cudaGetSymbolAddress((void**)&pWih, g_wihp);
    cudaGetSymbolAddress((void**)&pLp, g_Lp);
    cudaGetSymbolAddress((void**)&pR2t, g_R2t);
    cudaGetSymbolAddress((void**)&pVt, g_Vt);
    cudaGetSymbolAddress((void**)&pCemb, g_cemb);
    cudaGetSymbolAddress((void**)&pbC, g_bC);

    k_prep<<<1,256>>>(Ap, alpha);
    k_padw<<<(G3*ZP + 2*G3*HID + G3*32 + 2*G3 + 255)/256,256>>>(ewih, ewhh, dwhh, dwih, ebih, ebhh, dbih, dbhh);
    k_emb<<<(BN*16+255)/256,256>>>(x, fcw, fcb);
    k_adyn<<<dim3(BB,7),256>>>();
    k_topk<<<(BN+7)/8,256>>>(Ap);

    k_tfr<<<(BN*32+255)/256,256>>>(x, tw, tb, theta);
    k_tr<<<dim3(G3/32, (NA+31)/32, BB),256>>>();
    gemm_gru<3><<<dim3(4,BB),512,SMEMB>>>(pLp, KC, KC, pR2t, KC, nullptr, nullptr);
    gemm_gru<4><<<dim3(4,BB),512,SMEMB>>>(pLp, KC, KC, pVt, KC, nullptr, nullptr);

    k_fusion<<<(BTN*32+255)/256,256>>>(x, aw, ab, cw, cb);

    gemm_gru<0><<<BTN/64,512,SMEMB>>>(pZ, ZP, ZP, pWih, ZP, pbC, pGX);
    k_encdec<<<BN/64,512,ED_SMEM_W*4>>>(pGX, pCemb, x, dwih, ebhh, dbhh, ow, ob, out);
}